// round 15
// baseline (speedup 1.0000x reference)
#include <cuda_runtime.h>
#include <cuda_bf16.h>
#include <cstdint>

#define D 128
#define LAYERS 3
#define MAXN 100000
#define MAXE 1600000
#define MAXG 2048
#define TR 128         // fused rows per tile
#define PAD 136        // bf16 row stride (272B) -> conflict-free ldmatrix
#define BN_EPS 1e-5f
#define CHUNK 1024

// ---------------- scratch ----------------------------------------------------
__device__ float g_m[LAYERS][MAXN * D];   // pre-BN layer outputs
__device__ float g_colsum[LAYERS][D];
__device__ float g_colsq[LAYERS][D];
__device__ float g_bnsc[LAYERS][D];
__device__ float g_bnbt[LAYERS][D];
__device__ int   g_deg[MAXN];
__device__ int   g_fill[MAXN];
__device__ int   g_rowPtr[MAXN + 1];
__device__ int   g_chunkSum[(MAXN + CHUNK - 1) / CHUNK];
__device__ int   g_chunkOff[(MAXN + CHUNK - 1) / CHUNK];
__device__ int   g_csrSrc[MAXE];
__device__ int   g_gstart[MAXG + 1];

// ---------------- CSR build --------------------------------------------------

__global__ void csr_zero_kernel(int n)
{
    int i = blockIdx.x * blockDim.x + threadIdx.x;
    if (i < n) { g_deg[i] = 0; g_fill[i] = 0; }
    if (i < LAYERS * D) {
        ((float*)g_colsum)[i] = 0.f;
        ((float*)g_colsq)[i] = 0.f;
    }
}

__global__ void csr_hist_kernel(const int* __restrict__ ei, int ne)
{
    int e = blockIdx.x * blockDim.x + threadIdx.x;
    if (e < ne) atomicAdd(&g_deg[ei[ne + e]], 1);
}

__global__ void chunk_sum_kernel(int n)
{
    __shared__ int sh[256];
    int base = blockIdx.x * CHUNK;
    int s = 0;
    for (int j = threadIdx.x; j < CHUNK; j += 256) {
        int i = base + j;
        s += (i < n) ? g_deg[i] : 0;
    }
    sh[threadIdx.x] = s; __syncthreads();
    for (int m = 128; m > 0; m >>= 1) {
        if (threadIdx.x < m) sh[threadIdx.x] += sh[threadIdx.x + m];
        __syncthreads();
    }
    if (threadIdx.x == 0) g_chunkSum[blockIdx.x] = sh[0];
}

__global__ void chunk_scan_kernel(int nc, int n)
{
    __shared__ int sh[128];
    int t = threadIdx.x;
    int v = (t < nc) ? g_chunkSum[t] : 0;
    sh[t] = v; __syncthreads();
    for (int off = 1; off < 128; off <<= 1) {
        int x = 0;
        if (t >= off) x = sh[t - off];
        __syncthreads();
        sh[t] += x;
        __syncthreads();
    }
    if (t < nc) g_chunkOff[t] = sh[t] - v;
    if (t == 127) g_rowPtr[n] = sh[127];
}

__global__ void fill_rowptr_kernel(int n)
{
    __shared__ int sh[CHUNK];
    int t = threadIdx.x;
    int i = blockIdx.x * CHUNK + t;
    int v = (i < n) ? g_deg[i] : 0;
    sh[t] = v; __syncthreads();
    for (int off = 1; off < CHUNK; off <<= 1) {
        int x = 0;
        if (t >= off) x = sh[t - off];
        __syncthreads();
        sh[t] += x;
        __syncthreads();
    }
    if (i < n) g_rowPtr[i] = g_chunkOff[blockIdx.x] + sh[t] - v;
}

__global__ void csr_bucket_kernel(const int* __restrict__ ei, int ne)
{
    int e = blockIdx.x * blockDim.x + threadIdx.x;
    if (e >= ne) return;
    int s = ei[e], d = ei[ne + e];
    int pos = g_rowPtr[d] + atomicAdd(&g_fill[d], 1);
    g_csrSrc[pos] = s;
}

__global__ void gstart_kernel(const int* __restrict__ batch, int n, int G)
{
    int i = blockIdx.x * blockDim.x + threadIdx.x;
    if (i >= n) return;
    int b = batch[i];
    int prev = (i == 0) ? -1 : batch[i - 1];
    for (int g = prev + 1; g <= b; g++) g_gstart[g] = i;
    if (i == n - 1)
        for (int g = b + 1; g <= G; g++) g_gstart[g] = n;
}

// per-layer BN coefficients from accumulated stats (1 block, 128 threads)
__global__ void bn_stats_kernel(int layer, const float* __restrict__ gamma,
                                const float* __restrict__ beta, float invN)
{
    int c = threadIdx.x;
    float mean = g_colsum[layer][c] * invN;
    float var = g_colsq[layer][c] * invN - mean * mean;
    float sc = gamma[c] * rsqrtf(var + BN_EPS);
    g_bnsc[layer][c] = sc;
    g_bnbt[layer][c] = beta[c] - sc * mean;
}

// ---------------- bf16 split helpers -----------------------------------------
__device__ __forceinline__ uint2 split_hi(float4 v)
{
    unsigned u0 = __bfloat16_as_ushort(__float2bfloat16(v.x));
    unsigned u1 = __bfloat16_as_ushort(__float2bfloat16(v.y));
    unsigned u2 = __bfloat16_as_ushort(__float2bfloat16(v.z));
    unsigned u3 = __bfloat16_as_ushort(__float2bfloat16(v.w));
    return make_uint2(u0 | (u1 << 16), u2 | (u3 << 16));
}
__device__ __forceinline__ uint2 split_lo(float4 v)
{
    float r0 = v.x - __bfloat162float(__float2bfloat16(v.x));
    float r1 = v.y - __bfloat162float(__float2bfloat16(v.y));
    float r2 = v.z - __bfloat162float(__float2bfloat16(v.z));
    float r3 = v.w - __bfloat162float(__float2bfloat16(v.w));
    unsigned u0 = __bfloat16_as_ushort(__float2bfloat16(r0));
    unsigned u1 = __bfloat16_as_ushort(__float2bfloat16(r1));
    unsigned u2 = __bfloat16_as_ushort(__float2bfloat16(r2));
    unsigned u3 = __bfloat16_as_ushort(__float2bfloat16(r3));
    return make_uint2(u0 | (u1 << 16), u2 | (u3 << 16));
}

// ---- fused gather + MLP -----------------------------------------------------
__device__ __forceinline__ void mma16816(float* d, const unsigned* a,
                                         const unsigned* b)
{
    asm volatile(
        "mma.sync.aligned.m16n8k16.row.col.f32.bf16.bf16.f32 "
        "{%0,%1,%2,%3}, {%4,%5,%6,%7}, {%8,%9}, {%0,%1,%2,%3};"
        : "+f"(d[0]), "+f"(d[1]), "+f"(d[2]), "+f"(d[3])
        : "r"(a[0]), "r"(a[1]), "r"(a[2]), "r"(a[3]), "r"(b[0]), "r"(b[1]));
}

// R11's measured-good warp GEMM: 32x32 tile, x2 B loads
__device__ __forceinline__ void warp_gemm_128(
    const __nv_bfloat16* Ah, const __nv_bfloat16* Al,
    const __nv_bfloat16* Bh, const __nv_bfloat16* Bl,
    int rowSub, int colQ, int aRowOff, int aColOff, int bRowOff, int bColOff,
    float acc[2][4][4])
{
#pragma unroll
    for (int rs = 0; rs < 2; rs++)
#pragma unroll
        for (int nn = 0; nn < 4; nn++)
#pragma unroll
            for (int u = 0; u < 4; u++) acc[rs][nn][u] = 0.f;

#pragma unroll
    for (int k0 = 0; k0 < D; k0 += 16) {
        unsigned ah[2][4], al[2][4];
#pragma unroll
        for (int rs = 0; rs < 2; rs++) {
            const __nv_bfloat16* pa =
                Ah + (rowSub + rs * 16 + aRowOff) * PAD + k0 + aColOff;
            unsigned sa = (unsigned)__cvta_generic_to_shared(pa);
            asm volatile("ldmatrix.sync.aligned.m8n8.x4.shared.b16 "
                         "{%0,%1,%2,%3}, [%4];"
                         : "=r"(ah[rs][0]), "=r"(ah[rs][1]),
                           "=r"(ah[rs][2]), "=r"(ah[rs][3]) : "r"(sa));
            const __nv_bfloat16* pl =
                Al + (rowSub + rs * 16 + aRowOff) * PAD + k0 + aColOff;
            unsigned sl = (unsigned)__cvta_generic_to_shared(pl);
            asm volatile("ldmatrix.sync.aligned.m8n8.x4.shared.b16 "
                         "{%0,%1,%2,%3}, [%4];"
                         : "=r"(al[rs][0]), "=r"(al[rs][1]),
                           "=r"(al[rs][2]), "=r"(al[rs][3]) : "r"(sl));
        }
        unsigned bh[4][2], bl[4][2];
#pragma unroll
        for (int nn = 0; nn < 4; nn++) {
            const __nv_bfloat16* pb =
                Bh + (colQ + nn * 8 + bRowOff) * PAD + k0 + bColOff;
            unsigned sbh = (unsigned)__cvta_generic_to_shared(pb);
            asm volatile("ldmatrix.sync.aligned.m8n8.x2.shared.b16 "
                         "{%0,%1}, [%2];"
                         : "=r"(bh[nn][0]), "=r"(bh[nn][1]) : "r"(sbh));
            const __nv_bfloat16* pbl =
                Bl + (colQ + nn * 8 + bRowOff) * PAD + k0 + bColOff;
            unsigned sbl = (unsigned)__cvta_generic_to_shared(pbl);
            asm volatile("ldmatrix.sync.aligned.m8n8.x2.shared.b16 "
                         "{%0,%1}, [%2];"
                         : "=r"(bl[nn][0]), "=r"(bl[nn][1]) : "r"(sbl));
        }
#pragma unroll
        for (int rs = 0; rs < 2; rs++)
#pragma unroll
            for (int nn = 0; nn < 4; nn++) {
                mma16816(acc[rs][nn], ah[rs], bh[nn]);
                mma16816(acc[rs][nn], ah[rs], bl[nn]);
                mma16816(acc[rs][nn], al[rs], bh[nn]);
            }
    }
}

// warp gathers 8 rows (next tile) into pf registers; CSR walk, paired loads
__device__ __forceinline__ void gather_tile(
    const float* __restrict__ h, int row0, int n, int lane, int warp,
    int layer, float4 sc4, float4 bt4, float4 pf[8])
{
#pragma unroll
    for (int j = 0; j < 8; j++) {
        int gr = row0 + warp * 8 + j;
        float4 acc = make_float4(0.f, 0.f, 0.f, 0.f);
        if (gr < n) {
            int st = g_rowPtr[gr], en = g_rowPtr[gr + 1];
            acc = *(const float4*)(h + (size_t)gr * D + lane * 4);  // self
            for (int base = st; base < en; base += 32) {
                int idx = base + lane;
                int sv = (idx < en) ? g_csrSrc[idx] : 0;
                int cnt = min(32, en - base);
                int jj = 0;
                for (; jj + 1 < cnt; jj += 2) {
                    int s0 = __shfl_sync(0xFFFFFFFFu, sv, jj);
                    int s1 = __shfl_sync(0xFFFFFFFFu, sv, jj + 1);
                    float4 v0 = *(const float4*)(h + (size_t)s0 * D + lane * 4);
                    float4 v1 = *(const float4*)(h + (size_t)s1 * D + lane * 4);
                    acc.x += v0.x + v1.x; acc.y += v0.y + v1.y;
                    acc.z += v0.z + v1.z; acc.w += v0.w + v1.w;
                }
                if (jj < cnt) {
                    int s0 = __shfl_sync(0xFFFFFFFFu, sv, jj);
                    float4 v0 = *(const float4*)(h + (size_t)s0 * D + lane * 4);
                    acc.x += v0.x; acc.y += v0.y; acc.z += v0.z; acc.w += v0.w;
                }
            }
            if (layer > 0) {
                float cnt1 = (float)(en - st + 1);
                acc.x = sc4.x * acc.x + cnt1 * bt4.x;
                acc.y = sc4.y * acc.y + cnt1 * bt4.y;
                acc.z = sc4.z * acc.z + cnt1 * bt4.z;
                acc.w = sc4.w * acc.w + cnt1 * bt4.w;
            }
        }
        pf[j] = acc;
    }
}

__global__ __launch_bounds__(512) void mlp_fused_kernel(
    const float* __restrict__ hsrc,           // x (layer0) or g_m[layer-1]
    const float* __restrict__ W1, const float* __restrict__ b1,
    const float* __restrict__ W2, const float* __restrict__ b2,
    float* __restrict__ C, int layer, int n, int numTiles)
{
    extern __shared__ __nv_bfloat16 sb[];
    __nv_bfloat16* Ah  = sb;                    // [128][PAD]; reused as M1 hi
    __nv_bfloat16* Al  = Ah + TR * PAD;         // [128][PAD]; reused as M1 lo
    __nv_bfloat16* W1h = Al + TR * PAD;         // [128][PAD] transposed [n][k]
    __nv_bfloat16* W1l = W1h + D * PAD;
    __nv_bfloat16* W2h = W1l + D * PAD;
    __nv_bfloat16* W2l = W2h + D * PAD;

    int t = threadIdx.x;
    int warp = t >> 5, lane = t & 31;

    // load + split + transpose both weights (once per block)
    for (int i = t; i < D * D; i += 512) {
        int k = i >> 7, nn = i & 127;
        float w = W1[i];
        __nv_bfloat16 hh = __float2bfloat16(w);
        W1h[nn * PAD + k] = hh;
        W1l[nn * PAD + k] = __float2bfloat16(w - __bfloat162float(hh));
        float w2 = W2[i];
        __nv_bfloat16 hh2 = __float2bfloat16(w2);
        W2h[nn * PAD + k] = hh2;
        W2l[nn * PAD + k] = __float2bfloat16(w2 - __bfloat162float(hh2));
    }

    int rowSub = (warp & 3) * 32;
    int colQ   = (warp >> 2) * 32;
    int cb     = (lane & 3) * 2;
    int quad   = lane >> 3, lrow = lane & 7;
    int l16    = lane & 15;
    int aRowOff = (quad & 1) * 8 + lrow;
    int aColOff = (quad >> 1) * 8;
    int bRowOff = l16 & 7;
    int bColOff = (l16 >> 3) * 8;

    float4 sc4 = make_float4(1.f, 1.f, 1.f, 1.f);
    float4 bt4 = make_float4(0.f, 0.f, 0.f, 0.f);
    if (layer > 0) {
        sc4 = *(const float4*)(&g_bnsc[layer - 1][lane * 4]);
        bt4 = *(const float4*)(&g_bnbt[layer - 1][lane * 4]);
    }

    float b1_r[4][2], b2_r[4][2];
#pragma unroll
    for (int nn = 0; nn < 4; nn++) {
        b1_r[nn][0] = b1[colQ + nn * 8 + cb];
        b1_r[nn][1] = b1[colQ + nn * 8 + cb + 1];
        b2_r[nn][0] = b2[colQ + nn * 8 + cb];
        b2_r[nn][1] = b2[colQ + nn * 8 + cb + 1];
    }

    float ss[8], sq[8];
#pragma unroll
    for (int i = 0; i < 8; i++) { ss[i] = 0.f; sq[i] = 0.f; }

    // prologue: gather first tile into registers
    float4 pf[8];
    int tile = blockIdx.x;
    if (tile < numTiles)
        gather_tile(hsrc, tile * TR, n, lane, warp, layer, sc4, bt4, pf);

    __syncthreads();   // weights ready

    for (; tile < numTiles; tile += gridDim.x) {
        int row0 = tile * TR;

        // commit gathered tile: split hi/lo into A smem
#pragma unroll
        for (int j = 0; j < 8; j++) {
            int r = warp * 8 + j;
            *(uint2*)(Ah + r * PAD + lane * 4) = split_hi(pf[j]);
            *(uint2*)(Al + r * PAD + lane * 4) = split_lo(pf[j]);
        }
        __syncthreads();

        // GEMM1: M1 = relu(A @ W1 + b1)
        float acc[2][4][4];
        warp_gemm_128(Ah, Al, W1h, W1l, rowSub, colQ,
                      aRowOff, aColOff, bRowOff, bColOff, acc);
        __syncthreads();   // all A reads done; safe to overwrite with M1

#pragma unroll
        for (int rs = 0; rs < 2; rs++) {
            int rA = rowSub + rs * 16 + (lane >> 2);
#pragma unroll
            for (int nn = 0; nn < 4; nn++) {
                int c = colQ + nn * 8 + cb;
#pragma unroll
                for (int hb = 0; hb < 2; hb++) {
                    int rr = rA + hb * 8;
                    float o0 = fmaxf(acc[rs][nn][hb * 2 + 0] + b1_r[nn][0], 0.f);
                    float o1 = fmaxf(acc[rs][nn][hb * 2 + 1] + b1_r[nn][1], 0.f);
                    __nv_bfloat16 h0 = __float2bfloat16(o0);
                    __nv_bfloat16 h1 = __float2bfloat16(o1);
                    unsigned hp = __bfloat16_as_ushort(h0) |
                                  ((unsigned)__bfloat16_as_ushort(h1) << 16);
                    unsigned lp = __bfloat16_as_ushort(
                                      __float2bfloat16(o0 - __bfloat162float(h0))) |
                                  ((unsigned)__bfloat16_as_ushort(
                                      __float2bfloat16(o1 - __bfloat162float(h1))) << 16);
                    *(unsigned*)(Ah + rr * PAD + c) = hp;
                    *(unsigned*)(Al + rr * PAD + c) = lp;
                }
            }
        }
        __syncthreads();   // M1 visible to all warps

        // GEMM2: m = relu(M1 @ W2 + b2) -> global + stats
        warp_gemm_128(Ah, Al, W2h, W2l, rowSub, colQ,
                      aRowOff, aColOff, bRowOff, bColOff, acc);

#pragma unroll
        for (int rs = 0; rs < 2; rs++) {
            int rA = row0 + rowSub + rs * 16 + (lane >> 2);
#pragma unroll
            for (int nn = 0; nn < 4; nn++) {
                int c = colQ + nn * 8 + cb;
#pragma unroll
                for (int hb = 0; hb < 2; hb++) {
                    int rr = rA + hb * 8;
                    if (rr >= n) continue;
                    float o0 = fmaxf(acc[rs][nn][hb * 2 + 0] + b2_r[nn][0], 0.f);
                    float o1 = fmaxf(acc[rs][nn][hb * 2 + 1] + b2_r[nn][1], 0.f);
                    *(float2*)(C + (size_t)rr * D + c) = make_float2(o0, o1);
                    ss[nn * 2 + 0] += o0; sq[nn * 2 + 0] += o0 * o0;
                    ss[nn * 2 + 1] += o1; sq[nn * 2 + 1] += o1 * o1;
                }
            }
        }

        // gather next tile (overlaps other warps' MMA/epilogue work)
        int ntile = tile + gridDim.x;
        if (ntile < numTiles)
            gather_tile(hsrc, ntile * TR, n, lane, warp, layer, sc4, bt4, pf);

        __syncthreads();   // M1 reads done before next commit overwrites A
    }

    // flush BN stats (per-layer slot)
#pragma unroll
    for (int i = 0; i < 8; i++) {
#pragma unroll
        for (int m = 4; m <= 16; m <<= 1) {
            ss[i] += __shfl_xor_sync(0xFFFFFFFFu, ss[i], m);
            sq[i] += __shfl_xor_sync(0xFFFFFFFFu, sq[i], m);
        }
    }
    if (lane < 4) {
#pragma unroll
        for (int nn = 0; nn < 4; nn++) {
            int c = colQ + nn * 8 + lane * 2;
            atomicAdd(&g_colsum[layer][c + 0], ss[nn * 2 + 0]);
            atomicAdd(&g_colsum[layer][c + 1], ss[nn * 2 + 1]);
            atomicAdd(&g_colsq[layer][c + 0], sq[nn * 2 + 0]);
            atomicAdd(&g_colsq[layer][c + 1], sq[nn * 2 + 1]);
        }
    }
}

// one block per graph; applies BN affine on the fly; no atomics
__global__ void seg_max_kernel(float* __restrict__ out, int n)
{
    int g = blockIdx.x;
    int col = threadIdx.x;
    int s = g_gstart[g], e = g_gstart[g + 1];
    float sc0 = g_bnsc[0][col], bt0 = g_bnbt[0][col];
    float sc1 = g_bnsc[1][col], bt1 = g_bnbt[1][col];
    float sc2 = g_bnsc[2][col], bt2 = g_bnbt[2][col];
    float m0 = -3.402823466e+38f, m1 = m0, m2 = m0;
    for (int node = s; node < e; node++) {
        m0 = fmaxf(m0, sc0 * g_m[0][(size_t)node * D + col] + bt0);
        m1 = fmaxf(m1, sc1 * g_m[1][(size_t)node * D + col] + bt1);
        m2 = fmaxf(m2, sc2 * g_m[2][(size_t)node * D + col] + bt2);
    }
    out[g * (LAYERS * D) + col] = m0;
    out[g * (LAYERS * D) + D + col] = m1;
    out[g * (LAYERS * D) + 2 * D + col] = m2;
}

// ---------------- launch -----------------------------------------------------

extern "C" void kernel_launch(void* const* d_in, const int* in_sizes, int n_in,
                              void* d_out, int out_size)
{
    const float* x     = (const float*)d_in[0];
    const int*   ei    = (const int*)d_in[1];
    const int*   batch = (const int*)d_in[2];
    const float* W1    = (const float*)d_in[3];
    const float* b1    = (const float*)d_in[4];
    const float* W2    = (const float*)d_in[5];
    const float* b2    = (const float*)d_in[6];
    const float* gamma = (const float*)d_in[7];
    const float* beta  = (const float*)d_in[8];
    float* out = (float*)d_out;

    int n  = in_sizes[0] / D;
    int ne = in_sizes[1] / 2;
    int G  = out_size / (LAYERS * D);
    float invN = 1.0f / (float)n;

    float *p_m;
    cudaGetSymbolAddress((void**)&p_m, g_m);

    int smem = (2 * TR * PAD + 4 * D * PAD) * (int)sizeof(__nv_bfloat16); // 208896
    cudaFuncSetAttribute(mlp_fused_kernel,
                         cudaFuncAttributeMaxDynamicSharedMemorySize, smem);

    int numTiles = (n + TR - 1) / TR;
    int nc = (n + CHUNK - 1) / CHUNK;

    // CSR build (once; reused across layers) + stats zero
    csr_zero_kernel<<<(n + 255) / 256, 256>>>(n);
    csr_hist_kernel<<<(ne + 255) / 256, 256>>>(ei, ne);
    chunk_sum_kernel<<<nc, 256>>>(n);
    chunk_scan_kernel<<<1, 128>>>(nc, n);
    fill_rowptr_kernel<<<nc, CHUNK>>>(n);
    csr_bucket_kernel<<<(ne + 255) / 256, 256>>>(ei, ne);
    gstart_kernel<<<(n + 255) / 256, 256>>>(batch, n, G);

    for (int i = 0; i < LAYERS; i++) {
        const float* hsrc = (i == 0) ? x : (p_m + (size_t)(i - 1) * MAXN * D);
        mlp_fused_kernel<<<148, 512, smem>>>(
            hsrc, W1 + i * D * D, b1 + i * D,
            W2 + i * D * D, b2 + i * D,
            p_m + (size_t)i * MAXN * D, i, n, numTiles);
        bn_stats_kernel<<<1, D>>>(i, gamma + i * D, beta + i * D, invN);
    }

    seg_max_kernel<<<G, D>>>(out, n);
}

// round 17
// speedup vs baseline: 1.4862x; 1.4862x over previous
#include <cuda_runtime.h>
#include <cuda_bf16.h>
#include <cstdint>

#define D 128
#define LAYERS 3
#define MAXN 100000
#define MAXE 1600000
#define MAXG 2048
#define TR 128         // fused GEMM rows per tile
#define PAD 136        // bf16 row stride (272B) -> conflict-free ldmatrix
#define BN_EPS 1e-5f
#define CHUNK 1024

// ---------------- scratch ----------------------------------------------------
__device__ float         g_m[LAYERS][MAXN * D];   // pre-BN layer outputs
__device__ __nv_bfloat16 g_aggH[MAXN * D];
__device__ __nv_bfloat16 g_aggL[MAXN * D];
__device__ float         g_colsum[D];
__device__ float         g_colsq[D];
__device__ float         g_bnsc[LAYERS][D];
__device__ float         g_bnbt[LAYERS][D];
__device__ int           g_deg[MAXN];
__device__ int           g_fill[MAXN];
__device__ int           g_rowPtr[MAXN + 1];
__device__ int           g_chunkSum[(MAXN + CHUNK - 1) / CHUNK];
__device__ int           g_chunkOff[(MAXN + CHUNK - 1) / CHUNK];
__device__ int           g_csrSrc[MAXE];
__device__ int           g_gstart[MAXG + 1];

// ---------------- CSR build --------------------------------------------------

__global__ void csr_zero_kernel(int n)
{
    int i = blockIdx.x * blockDim.x + threadIdx.x;
    if (i < n) { g_deg[i] = 0; g_fill[i] = 0; }
}

__global__ void csr_hist_kernel(const int* __restrict__ ei, int ne)
{
    int e = blockIdx.x * blockDim.x + threadIdx.x;
    if (e < ne) atomicAdd(&g_deg[ei[ne + e]], 1);
}

__global__ void chunk_sum_kernel(int n)
{
    __shared__ int sh[256];
    int base = blockIdx.x * CHUNK;
    int s = 0;
    for (int j = threadIdx.x; j < CHUNK; j += 256) {
        int i = base + j;
        s += (i < n) ? g_deg[i] : 0;
    }
    sh[threadIdx.x] = s; __syncthreads();
    for (int m = 128; m > 0; m >>= 1) {
        if (threadIdx.x < m) sh[threadIdx.x] += sh[threadIdx.x + m];
        __syncthreads();
    }
    if (threadIdx.x == 0) g_chunkSum[blockIdx.x] = sh[0];
}

__global__ void chunk_scan_kernel(int nc, int n)
{
    __shared__ int sh[128];
    int t = threadIdx.x;
    int v = (t < nc) ? g_chunkSum[t] : 0;
    sh[t] = v; __syncthreads();
    for (int off = 1; off < 128; off <<= 1) {
        int x = 0;
        if (t >= off) x = sh[t - off];
        __syncthreads();
        sh[t] += x;
        __syncthreads();
    }
    if (t < nc) g_chunkOff[t] = sh[t] - v;
    if (t == 127) g_rowPtr[n] = sh[127];
}

__global__ void fill_rowptr_kernel(int n)
{
    __shared__ int sh[CHUNK];
    int t = threadIdx.x;
    int i = blockIdx.x * CHUNK + t;
    int v = (i < n) ? g_deg[i] : 0;
    sh[t] = v; __syncthreads();
    for (int off = 1; off < CHUNK; off <<= 1) {
        int x = 0;
        if (t >= off) x = sh[t - off];
        __syncthreads();
        sh[t] += x;
        __syncthreads();
    }
    if (i < n) g_rowPtr[i] = g_chunkOff[blockIdx.x] + sh[t] - v;
}

__global__ void csr_bucket_kernel(const int* __restrict__ ei, int ne)
{
    int e = blockIdx.x * blockDim.x + threadIdx.x;
    if (e >= ne) return;
    int s = ei[e], d = ei[ne + e];
    int pos = g_rowPtr[d] + atomicAdd(&g_fill[d], 1);
    g_csrSrc[pos] = s;
}

__global__ void gstart_kernel(const int* __restrict__ batch, int n, int G)
{
    int i = blockIdx.x * blockDim.x + threadIdx.x;
    if (i >= n) return;
    int b = batch[i];
    int prev = (i == 0) ? -1 : batch[i - 1];
    for (int g = prev + 1; g <= b; g++) g_gstart[g] = i;
    if (i == n - 1)
        for (int g = b + 1; g <= G; g++) g_gstart[g] = n;
}

// ---------------- bf16 split helpers -----------------------------------------
__device__ __forceinline__ uint2 split_hi(float4 v)
{
    unsigned u0 = __bfloat16_as_ushort(__float2bfloat16(v.x));
    unsigned u1 = __bfloat16_as_ushort(__float2bfloat16(v.y));
    unsigned u2 = __bfloat16_as_ushort(__float2bfloat16(v.z));
    unsigned u3 = __bfloat16_as_ushort(__float2bfloat16(v.w));
    return make_uint2(u0 | (u1 << 16), u2 | (u3 << 16));
}
__device__ __forceinline__ uint2 split_lo(float4 v)
{
    float r0 = v.x - __bfloat162float(__float2bfloat16(v.x));
    float r1 = v.y - __bfloat162float(__float2bfloat16(v.y));
    float r2 = v.z - __bfloat162float(__float2bfloat16(v.z));
    float r3 = v.w - __bfloat162float(__float2bfloat16(v.w));
    unsigned u0 = __bfloat16_as_ushort(__float2bfloat16(r0));
    unsigned u1 = __bfloat16_as_ushort(__float2bfloat16(r1));
    unsigned u2 = __bfloat16_as_ushort(__float2bfloat16(r2));
    unsigned u3 = __bfloat16_as_ushort(__float2bfloat16(r3));
    return make_uint2(u0 | (u1 << 16), u2 | (u3 << 16));
}

// ---------------- gather: BN affine folded in, bf16 hi/lo out ----------------
__global__ void gather_kernel(const float* __restrict__ x, int layer, int n)
{
    int t = blockIdx.x * blockDim.x + threadIdx.x;
    if (blockIdx.x == 0 && threadIdx.x < D) {
        g_colsum[threadIdx.x] = 0.f;
        g_colsq[threadIdx.x] = 0.f;
    }
    int w = t >> 5;
    if (w >= n) return;
    int lane = t & 31;
    const float* h = (layer == 0) ? x : g_m[layer - 1];
    int start = g_rowPtr[w], end = g_rowPtr[w + 1];
    float4 acc = *(const float4*)(h + (size_t)w * D + lane * 4);
    for (int base = start; base < end; base += 32) {
        int idx = base + lane;
        int sv = (idx < end) ? g_csrSrc[idx] : 0;
        int cnt = min(32, end - base);
        for (int j = 0; j < cnt; j++) {
            int s = __shfl_sync(0xFFFFFFFFu, sv, j);
            float4 vv = *(const float4*)(h + (size_t)s * D + lane * 4);
            acc.x += vv.x; acc.y += vv.y; acc.z += vv.z; acc.w += vv.w;
        }
    }
    if (layer > 0) {
        float4 sc = *(const float4*)(&g_bnsc[layer - 1][lane * 4]);
        float4 bt = *(const float4*)(&g_bnbt[layer - 1][lane * 4]);
        float cnt1 = (float)(end - start + 1);
        acc.x = sc.x * acc.x + cnt1 * bt.x;
        acc.y = sc.y * acc.y + cnt1 * bt.y;
        acc.z = sc.z * acc.z + cnt1 * bt.z;
        acc.w = sc.w * acc.w + cnt1 * bt.w;
    }
    *(uint2*)(g_aggH + (size_t)w * D + lane * 4) = split_hi(acc);
    *(uint2*)(g_aggL + (size_t)w * D + lane * 4) = split_lo(acc);
}

__global__ void bn_stats_kernel(int layer, const float* __restrict__ gamma,
                                const float* __restrict__ beta, float invN)
{
    int c = threadIdx.x;
    float mean = g_colsum[c] * invN;
    float var = g_colsq[c] * invN - mean * mean;
    float sc = gamma[c] * rsqrtf(var + BN_EPS);
    g_bnsc[layer][c] = sc;
    g_bnbt[layer][c] = beta[c] - sc * mean;
}

// ---- fused MLP: m = relu(relu(A@W1+b1)@W2+b2), bf16x3 tensor cores ----------
__device__ __forceinline__ void mma16816(float* d, const unsigned* a,
                                         const unsigned* b)
{
    asm volatile(
        "mma.sync.aligned.m16n8k16.row.col.f32.bf16.bf16.f32 "
        "{%0,%1,%2,%3}, {%4,%5,%6,%7}, {%8,%9}, {%0,%1,%2,%3};"
        : "+f"(d[0]), "+f"(d[1]), "+f"(d[2]), "+f"(d[3])
        : "r"(a[0]), "r"(a[1]), "r"(a[2]), "r"(a[3]), "r"(b[0]), "r"(b[1]));
}

// warp computes acc[2][4][4] = 32x32 tile of Asrc(hi/lo) @ Bsrc(hi/lo, [n][k])
__device__ __forceinline__ void warp_gemm_128(
    const __nv_bfloat16* Ah, const __nv_bfloat16* Al,
    const __nv_bfloat16* Bh, const __nv_bfloat16* Bl,
    int rowSub, int colQ, int aRowOff, int aColOff, int bRowOff, int bColOff,
    float acc[2][4][4])
{
#pragma unroll
    for (int rs = 0; rs < 2; rs++)
#pragma unroll
        for (int nn = 0; nn < 4; nn++)
#pragma unroll
            for (int u = 0; u < 4; u++) acc[rs][nn][u] = 0.f;

#pragma unroll
    for (int k0 = 0; k0 < D; k0 += 16) {
        unsigned ah[2][4], al[2][4];
#pragma unroll
        for (int rs = 0; rs < 2; rs++) {
            const __nv_bfloat16* pa =
                Ah + (rowSub + rs * 16 + aRowOff) * PAD + k0 + aColOff;
            unsigned sa = (unsigned)__cvta_generic_to_shared(pa);
            asm volatile("ldmatrix.sync.aligned.m8n8.x4.shared.b16 "
                         "{%0,%1,%2,%3}, [%4];"
                         : "=r"(ah[rs][0]), "=r"(ah[rs][1]),
                           "=r"(ah[rs][2]), "=r"(ah[rs][3]) : "r"(sa));
            const __nv_bfloat16* pl =
                Al + (rowSub + rs * 16 + aRowOff) * PAD + k0 + aColOff;
            unsigned sl = (unsigned)__cvta_generic_to_shared(pl);
            asm volatile("ldmatrix.sync.aligned.m8n8.x4.shared.b16 "
                         "{%0,%1,%2,%3}, [%4];"
                         : "=r"(al[rs][0]), "=r"(al[rs][1]),
                           "=r"(al[rs][2]), "=r"(al[rs][3]) : "r"(sl));
        }
        unsigned bh[4][2], bl[4][2];
#pragma unroll
        for (int nn = 0; nn < 4; nn++) {
            const __nv_bfloat16* pb =
                Bh + (colQ + nn * 8 + bRowOff) * PAD + k0 + bColOff;
            unsigned sbh = (unsigned)__cvta_generic_to_shared(pb);
            asm volatile("ldmatrix.sync.aligned.m8n8.x2.shared.b16 "
                         "{%0,%1}, [%2];"
                         : "=r"(bh[nn][0]), "=r"(bh[nn][1]) : "r"(sbh));
            const __nv_bfloat16* pbl =
                Bl + (colQ + nn * 8 + bRowOff) * PAD + k0 + bColOff;
            unsigned sbl = (unsigned)__cvta_generic_to_shared(pbl);
            asm volatile("ldmatrix.sync.aligned.m8n8.x2.shared.b16 "
                         "{%0,%1}, [%2];"
                         : "=r"(bl[nn][0]), "=r"(bl[nn][1]) : "r"(sbl));
        }
#pragma unroll
        for (int rs = 0; rs < 2; rs++)
#pragma unroll
            for (int nn = 0; nn < 4; nn++) {
                mma16816(acc[rs][nn], ah[rs], bh[nn]);
                mma16816(acc[rs][nn], ah[rs], bl[nn]);
                mma16816(acc[rs][nn], al[rs], bh[nn]);
            }
    }
}

__global__ __launch_bounds__(512) void mlp_fused_kernel(
    const __nv_bfloat16* __restrict__ AH, const __nv_bfloat16* __restrict__ AL,
    const float* __restrict__ W1, const float* __restrict__ b1,
    const float* __restrict__ W2, const float* __restrict__ b2,
    float* __restrict__ C, int n, int numTiles)
{
    extern __shared__ __nv_bfloat16 sb[];
    __nv_bfloat16* Ah  = sb;                    // [128][PAD]; reused as M1 hi
    __nv_bfloat16* Al  = Ah + TR * PAD;         // [128][PAD]; reused as M1 lo
    __nv_bfloat16* W1h = Al + TR * PAD;         // [128][PAD] transposed [n][k]
    __nv_bfloat16* W1l = W1h + D * PAD;
    __nv_bfloat16* W2h = W1l + D * PAD;
    __nv_bfloat16* W2l = W2h + D * PAD;

    int t = threadIdx.x;
    int warp = t >> 5, lane = t & 31;

    // load + split + transpose both weights (once per block)
    for (int i = t; i < D * D; i += 512) {
        int k = i >> 7, nn = i & 127;
        float w = W1[i];
        __nv_bfloat16 hh = __float2bfloat16(w);
        W1h[nn * PAD + k] = hh;
        W1l[nn * PAD + k] = __float2bfloat16(w - __bfloat162float(hh));
        float w2 = W2[i];
        __nv_bfloat16 hh2 = __float2bfloat16(w2);
        W2h[nn * PAD + k] = hh2;
        W2l[nn * PAD + k] = __float2bfloat16(w2 - __bfloat162float(hh2));
    }

    int rowSub = (warp & 3) * 32;
    int colQ   = (warp >> 2) * 32;
    int cb     = (lane & 3) * 2;
    int quad   = lane >> 3, lrow = lane & 7;
    int l16    = lane & 15;
    int aRowOff = (quad & 1) * 8 + lrow;
    int aColOff = (quad >> 1) * 8;
    int bRowOff = l16 & 7;
    int bColOff = (l16 >> 3) * 8;

    float b1_r[4][2], b2_r[4][2];
#pragma unroll
    for (int nn = 0; nn < 4; nn++) {
        b1_r[nn][0] = b1[colQ + nn * 8 + cb];
        b1_r[nn][1] = b1[colQ + nn * 8 + cb + 1];
        b2_r[nn][0] = b2[colQ + nn * 8 + cb];
        b2_r[nn][1] = b2[colQ + nn * 8 + cb + 1];
    }

    float ss[8], sq[8];
#pragma unroll
    for (int i = 0; i < 8; i++) { ss[i] = 0.f; sq[i] = 0.f; }

    __syncthreads();

    for (int tile = blockIdx.x; tile < numTiles; tile += gridDim.x) {
        int row0 = tile * TR;

        // A fill: 128 rows x 16 chunks x 2 halves = 4096 x 16B via cp.async
#pragma unroll
        for (int j = 0; j < 8; j++) {
            int idx = t + j * 512;
            int half = idx >> 11;
            int r = (idx & 2047) >> 4;
            int ck = idx & 15;
            int gr = row0 + r;
            __nv_bfloat16* dst = (half ? Al : Ah) + r * PAD + ck * 8;
            if (gr < n) {
                const __nv_bfloat16* src =
                    (half ? AL : AH) + (size_t)gr * D + ck * 8;
                unsigned du = (unsigned)__cvta_generic_to_shared(dst);
                asm volatile("cp.async.cg.shared.global [%0], [%1], 16;"
                             :: "r"(du), "l"(src));
            } else {
                *(float4*)dst = make_float4(0.f, 0.f, 0.f, 0.f);
            }
        }
        asm volatile("cp.async.commit_group;");
        asm volatile("cp.async.wait_group 0;");
        __syncthreads();

        // GEMM1: M1 = relu(A @ W1 + b1)
        float acc[2][4][4];
        warp_gemm_128(Ah, Al, W1h, W1l, rowSub, colQ,
                      aRowOff, aColOff, bRowOff, bColOff, acc);
        __syncthreads();   // all A reads done; safe to overwrite with M1

#pragma unroll
        for (int rs = 0; rs < 2; rs++) {
            int rA = rowSub + rs * 16 + (lane >> 2);
#pragma unroll
            for (int nn = 0; nn < 4; nn++) {
                int c = colQ + nn * 8 + cb;
#pragma unroll
                for (int hb = 0; hb < 2; hb++) {
                    int rr = rA + hb * 8;
                    float o0 = fmaxf(acc[rs][nn][hb * 2 + 0] + b1_r[nn][0], 0.f);
                    float o1 = fmaxf(acc[rs][nn][hb * 2 + 1] + b1_r[nn][1], 0.f);
                    __nv_bfloat16 h0 = __float2bfloat16(o0);
                    __nv_bfloat16 h1 = __float2bfloat16(o1);
                    unsigned hp = __bfloat16_as_ushort(h0) |
                                  ((unsigned)__bfloat16_as_ushort(h1) << 16);
                    unsigned lp = __bfloat16_as_ushort(
                                      __float2bfloat16(o0 - __bfloat162float(h0))) |
                                  ((unsigned)__bfloat16_as_ushort(
                                      __float2bfloat16(o1 - __bfloat162float(h1))) << 16);
                    *(unsigned*)(Ah + rr * PAD + c) = hp;
                    *(unsigned*)(Al + rr * PAD + c) = lp;
                }
            }
        }
        __syncthreads();   // M1 visible to all warps

        // GEMM2: m = relu(M1 @ W2 + b2) -> global + stats
        warp_gemm_128(Ah, Al, W2h, W2l, rowSub, colQ,
                      aRowOff, aColOff, bRowOff, bColOff, acc);

#pragma unroll
        for (int rs = 0; rs < 2; rs++) {
            int rA = row0 + rowSub + rs * 16 + (lane >> 2);
#pragma unroll
            for (int nn = 0; nn < 4; nn++) {
                int c = colQ + nn * 8 + cb;
#pragma unroll
                for (int hb = 0; hb < 2; hb++) {
                    int rr = rA + hb * 8;
                    if (rr >= n) continue;
                    float o0 = fmaxf(acc[rs][nn][hb * 2 + 0] + b2_r[nn][0], 0.f);
                    float o1 = fmaxf(acc[rs][nn][hb * 2 + 1] + b2_r[nn][1], 0.f);
                    *(float2*)(C + (size_t)rr * D + c) = make_float2(o0, o1);
                    ss[nn * 2 + 0] += o0; sq[nn * 2 + 0] += o0 * o0;
                    ss[nn * 2 + 1] += o1; sq[nn * 2 + 1] += o1 * o1;
                }
            }
        }
        __syncthreads();   // M1 reads done before next tile overwrites
    }

    // flush BN stats
#pragma unroll
    for (int i = 0; i < 8; i++) {
#pragma unroll
        for (int m = 4; m <= 16; m <<= 1) {
            ss[i] += __shfl_xor_sync(0xFFFFFFFFu, ss[i], m);
            sq[i] += __shfl_xor_sync(0xFFFFFFFFu, sq[i], m);
        }
    }
    if (lane < 4) {
#pragma unroll
        for (int nn = 0; nn < 4; nn++) {
            int c = colQ + nn * 8 + lane * 2;
            atomicAdd(&g_colsum[c + 0], ss[nn * 2 + 0]);
            atomicAdd(&g_colsum[c + 1], ss[nn * 2 + 1]);
            atomicAdd(&g_colsq[c + 0], sq[nn * 2 + 0]);
            atomicAdd(&g_colsq[c + 1], sq[nn * 2 + 1]);
        }
    }
}

// one block per graph; applies BN affine on the fly; no atomics
__global__ void seg_max_kernel(float* __restrict__ out, int n)
{
    int g = blockIdx.x;
    int col = threadIdx.x;
    int s = g_gstart[g], e = g_gstart[g + 1];
    float sc0 = g_bnsc[0][col], bt0 = g_bnbt[0][col];
    float sc1 = g_bnsc[1][col], bt1 = g_bnbt[1][col];
    float sc2 = g_bnsc[2][col], bt2 = g_bnbt[2][col];
    float m0 = -3.402823466e+38f, m1 = m0, m2 = m0;
    for (int node = s; node < e; node++) {
        m0 = fmaxf(m0, sc0 * g_m[0][(size_t)node * D + col] + bt0);
        m1 = fmaxf(m1, sc1 * g_m[1][(size_t)node * D + col] + bt1);
        m2 = fmaxf(m2, sc2 * g_m[2][(size_t)node * D + col] + bt2);
    }
    out[g * (LAYERS * D) + col] = m0;
    out[g * (LAYERS * D) + D + col] = m1;
    out[g * (LAYERS * D) + 2 * D + col] = m2;
}

// ---------------- launch -----------------------------------------------------

extern "C" void kernel_launch(void* const* d_in, const int* in_sizes, int n_in,
                              void* d_out, int out_size)
{
    const float* x     = (const float*)d_in[0];
    const int*   ei    = (const int*)d_in[1];
    const int*   batch = (const int*)d_in[2];
    const float* W1    = (const float*)d_in[3];
    const float* b1    = (const float*)d_in[4];
    const float* W2    = (const float*)d_in[5];
    const float* b2    = (const float*)d_in[6];
    const float* gamma = (const float*)d_in[7];
    const float* beta  = (const float*)d_in[8];
    float* out = (float*)d_out;

    int n  = in_sizes[0] / D;
    int ne = in_sizes[1] / 2;
    int G  = out_size / (LAYERS * D);
    float invN = 1.0f / (float)n;

    __nv_bfloat16 *p_aggH, *p_aggL;
    float *p_m;
    cudaGetSymbolAddress((void**)&p_aggH, g_aggH);
    cudaGetSymbolAddress((void**)&p_aggL, g_aggL);
    cudaGetSymbolAddress((void**)&p_m,    g_m);

    int smem = (2 * TR * PAD + 4 * D * PAD) * (int)sizeof(__nv_bfloat16); // 208896
    cudaFuncSetAttribute(mlp_fused_kernel,
                         cudaFuncAttributeMaxDynamicSharedMemorySize, smem);

    int numTiles = (n + TR - 1) / TR;
    int nc = (n + CHUNK - 1) / CHUNK;

    // CSR build (once; reused across layers)
    csr_zero_kernel<<<(n + 255) / 256, 256>>>(n);
    csr_hist_kernel<<<(ne + 255) / 256, 256>>>(ei, ne);
    chunk_sum_kernel<<<nc, 256>>>(n);
    chunk_scan_kernel<<<1, 128>>>(nc, n);
    fill_rowptr_kernel<<<nc, CHUNK>>>(n);
    csr_bucket_kernel<<<(ne + 255) / 256, 256>>>(ei, ne);
    gstart_kernel<<<(n + 255) / 256, 256>>>(batch, n, G);

    int gatherBlocks = (n * 32 + 255) / 256;
    for (int i = 0; i < LAYERS; i++) {
        gather_kernel<<<gatherBlocks, 256>>>(x, i, n);
        mlp_fused_kernel<<<148, 512, smem>>>(
            p_aggH, p_aggL, W1 + i * D * D, b1 + i * D,
            W2 + i * D * D, b2 + i * D,
            p_m + (size_t)i * MAXN * D, n, numTiles);
        bn_stats_kernel<<<1, D>>>(i, gamma + i * D, beta + i * D, invN);
    }

    seg_max_kernel<<<G, D>>>(out, n);
}